// round 15
// baseline (speedup 1.0000x reference)
#include <cuda_runtime.h>

// Problem constants
#define Bn 4
#define Ln 2048
#define Dn 256
#define SLOTS 64
#define ROWS 192          // SLOTS * 3
#define MPAD 260          // padded stride (words): conflict-free 8-lane LDS.128 phases
#define TILE 56           // 4 * 37 = 148 blocks = one full wave
#define CH 8              // positions per chunk
#define NT 512            // 16 warps: 3 GEMM + 13 gather (all do argmax)
#define GT 96             // GEMM threads (3 warps)
#define TILES_PER_B 37
#define GBUF (CH * ROWS)  // 1536 words per G buffer
#define XBUF (CH * Dn)    // 2048 words per x buffer

// smem layout (words)
#define OFF_GSM  (ROWS * MPAD)                 // 49920 : gsm[2][8][192]
#define OFF_BIAS (OFF_GSM + 2 * GBUF)          // +3072
#define OFF_BEST (OFF_BIAS + ROWS)             // +192  : best[2][512] ushort = 512 words
#define OFF_XS   (OFF_BEST + 512)              // xs[2][8][256]
#define SMEM_WORDS (OFF_XS + 2 * XBUF)         // 57792 words = 231168 B

typedef unsigned long long u64;
typedef unsigned int u32;

__device__ __forceinline__ void bar_gemm() {   // 3 GEMM warps only
    asm volatile("bar.sync 1, 96;" ::: "memory");
}
__device__ __forceinline__ u64 fma2(u64 a, u64 b, u64 c) {
    u64 d;
    asm("fma.rn.f32x2 %0, %1, %2, %3;" : "=l"(d) : "l"(a), "l"(b), "l"(c));
    return d;
}
__device__ __forceinline__ u64 add2(u64 a, u64 b) {
    u64 d;
    asm("add.rn.f32x2 %0, %1, %2;" : "=l"(d) : "l"(a), "l"(b));
    return d;
}
__device__ __forceinline__ float hsum2(u64 a) {
    float lo, hi;
    asm("mov.b64 {%0,%1}, %2;" : "=f"(lo), "=f"(hi) : "l"(a));
    return lo + hi;
}
__device__ __forceinline__ u32 smem_u32(const void* p) {
    u32 a;
    asm("{ .reg .u64 t; cvta.to.shared.u64 t, %1; cvt.u32.u64 %0, t; }"
        : "=r"(a) : "l"(p));
    return a;
}
__device__ __forceinline__ void cpasync16(u32 dst, const void* src) {
    asm volatile("cp.async.cg.shared.global [%0], [%1], 16;" :: "r"(dst), "l"(src));
}

// full-K dot of gmem x-row with smem mem-row (for head seeds)
__device__ __forceinline__ float dot_row(const float* xrow, const float* mrow) {
    const ulonglong2* mp = (const ulonglong2*)mrow;
    const ulonglong2* xp = (const ulonglong2*)xrow;
    u64 a0 = 0ULL, a1 = 0ULL;
    #pragma unroll 8
    for (int d4 = 0; d4 < 64; ++d4) {
        ulonglong2 m = mp[d4], xv = xp[d4];
        a0 = fma2(m.x, xv.x, a0);
        a1 = fma2(m.y, xv.y, a1);
    }
    return hsum2(add2(a0, a1));
}

// GEMM slice: 4 columns (q, q+48, q+96, q+144), K-half (32 d4), 8 rows.
// kc1 writes gsm, bar, kc0 adds (combine folded; no part buffer).
__device__ __forceinline__ void gemm_chunk(
    const float* __restrict__ xs,
    const float* __restrict__ mem_s,
    float* __restrict__ gdst, int d4b, int q, int kc)
{
    const ulonglong2* xp  = (const ulonglong2*)xs;
    const ulonglong2* mp0 = (const ulonglong2*)(mem_s + q * MPAD);
    const ulonglong2* mp1 = (const ulonglong2*)(mem_s + (q + 48) * MPAD);
    const ulonglong2* mp2 = (const ulonglong2*)(mem_s + (q + 96) * MPAD);
    const ulonglong2* mp3 = (const ulonglong2*)(mem_s + (q + 144) * MPAD);
    u64 a0[8], a1[8], a2[8], a3[8];
    #pragma unroll
    for (int r = 0; r < 8; r++) { a0[r] = 0ULL; a1[r] = 0ULL; a2[r] = 0ULL; a3[r] = 0ULL; }
    #pragma unroll 2
    for (int d4 = d4b; d4 < d4b + 32; ++d4) {
        ulonglong2 m0 = mp0[d4];
        ulonglong2 m1 = mp1[d4];
        ulonglong2 m2 = mp2[d4];
        ulonglong2 m3 = mp3[d4];
        #pragma unroll
        for (int r = 0; r < 8; r++) {
            ulonglong2 xv = xp[r * 64 + d4];   // warp-uniform broadcast LDS.128
            a0[r] = fma2(m0.x, xv.x, a0[r]);
            a0[r] = fma2(m0.y, xv.y, a0[r]);
            a1[r] = fma2(m1.x, xv.x, a1[r]);
            a1[r] = fma2(m1.y, xv.y, a1[r]);
            a2[r] = fma2(m2.x, xv.x, a2[r]);
            a2[r] = fma2(m2.y, xv.y, a2[r]);
            a3[r] = fma2(m3.x, xv.x, a3[r]);
            a3[r] = fma2(m3.y, xv.y, a3[r]);
        }
    }
    if (kc == 1) {
        #pragma unroll
        for (int r = 0; r < 8; r++) {
            gdst[r * ROWS + q]       = hsum2(a0[r]);
            gdst[r * ROWS + q + 48]  = hsum2(a1[r]);
            gdst[r * ROWS + q + 96]  = hsum2(a2[r]);
            gdst[r * ROWS + q + 144] = hsum2(a3[r]);
        }
    }
    bar_gemm();
    if (kc == 0) {
        #pragma unroll
        for (int r = 0; r < 8; r++) {
            gdst[r * ROWS + q]       += hsum2(a0[r]);
            gdst[r * ROWS + q + 48]  += hsum2(a1[r]);
            gdst[r * ROWS + q + 96]  += hsum2(a2[r]);
            gdst[r * ROWS + q + 144] += hsum2(a3[r]);
        }
    }
}

// gather one (p, d4): sum 64 selected rows (ushort premult indices, broadcast)
__device__ __forceinline__ void gather_one(
    const float* __restrict__ mem_s, const unsigned short* __restrict__ bp,
    float* __restrict__ outp, int d4)
{
    const uint4* ip = (const uint4*)bp;        // 8 x uint4 = 64 ushorts
    u64 ax[4] = {0ULL, 0ULL, 0ULL, 0ULL};
    u64 ay[4] = {0ULL, 0ULL, 0ULL, 0ULL};
    #pragma unroll
    for (int g = 0; g < 8; g++) {
        uint4 w = ip[g];                       // warp-uniform broadcast
        int q = g & 3;
        ulonglong2 v;
        #define PNM_ROW(IDX) \
            v = ((const ulonglong2*)(mem_s + (IDX)))[d4]; \
            ax[q] = add2(ax[q], v.x); ay[q] = add2(ay[q], v.y);
        PNM_ROW(w.x & 0xFFFFu)  PNM_ROW(w.x >> 16)
        PNM_ROW(w.y & 0xFFFFu)  PNM_ROW(w.y >> 16)
        PNM_ROW(w.z & 0xFFFFu)  PNM_ROW(w.z >> 16)
        PNM_ROW(w.w & 0xFFFFu)  PNM_ROW(w.w >> 16)
        #undef PNM_ROW
    }
    u64 s0 = add2(add2(ax[0], ax[1]), add2(ax[2], ax[3]));
    u64 s1 = add2(add2(ay[0], ay[1]), add2(ay[2], ay[3]));
    float x0, x1, y0, y1;
    asm("mov.b64 {%0,%1}, %2;" : "=f"(x0), "=f"(x1) : "l"(s0));
    asm("mov.b64 {%0,%1}, %2;" : "=f"(y0), "=f"(y1) : "l"(s1));
    ((float4*)outp)[d4] = make_float4(x0, x1, y0, y1);
}

__global__ void __launch_bounds__(NT, 1)
pnm_kernel(const float* __restrict__ x,
           const float* __restrict__ mem,
           const float* __restrict__ bias,
           float* __restrict__ out)
{
    extern __shared__ float smem[];
    float* mem_s  = smem;                               // [ROWS][MPAD]
    float* gsm    = smem + OFF_GSM;                     // [2][8][192]
    float* bias_s = smem + OFF_BIAS;                    // [192]
    unsigned short* best_s = (unsigned short*)(smem + OFF_BEST); // [2][512]
    float* xs     = smem + OFF_XS;                      // [2][8][256]

    const int tid  = threadIdx.x;
    const int b    = blockIdx.x / TILES_PER_B;
    const int l0   = (blockIdx.x % TILES_PER_B) * TILE;
    const int lend = (l0 + TILE < Ln) ? (l0 + TILE) : Ln;
    const int nc   = (lend - l0) / CH;                  // 7 or 4 (always exact)

    const float* xb = x + (size_t)b * Ln * Dn;
    const size_t orow0 = (size_t)b * Ln;

    // ---- prologue 1: stage mem_s + bias + xs[0] + xs[1] ----
    for (int i = tid; i < ROWS * (Dn / 4); i += NT) {
        int r = i >> 6, c = i & 63;
        ((float4*)(mem_s + r * MPAD))[c] = ((const float4*)mem)[i];
    }
    if (tid < ROWS) bias_s[tid] = bias[tid];
    {
        int r = tid >> 6, c = tid & 63;
        ((float4*)(xs + r * Dn))[c] =
            ((const float4*)(xb + (size_t)(l0 + r) * Dn))[c];
        ((float4*)(xs + XBUF + r * Dn))[c] =
            ((const float4*)(xb + (size_t)(l0 + CH + r) * Dn))[c];
    }
    __syncthreads();

    // GEMM decomposition: 96 threads = 48 col-quads x 2 K-halves (kc warp-uniform)
    const bool is_gemm = (tid < GT);
    const int  q  = tid % 48;
    const int  kc = (tid / 48) & 1;
    const int  d4b = kc * 32;

    // argmax identity (fixed across phases; h-regs live for tid<128)
    const int pa = tid >> 6;                   // position within chunk
    const int m3 = (tid & 63) * 3;
    float h0 = 0.f, h1 = 0.f;                  // boundary G (p==0: n0,n1; p==1: n0)

    // ---- prologue 2: h seeds (tid<128) + GEMM chunk 0 -> gsm[0] ----
    if (tid < 128) {
        if (pa == 0) {
            if (l0 >= 2) h0 = dot_row(xb + (size_t)(l0 - 2) * Dn, mem_s + m3 * MPAD);
            if (l0 >= 1) h1 = dot_row(xb + (size_t)(l0 - 1) * Dn, mem_s + (m3 + 1) * MPAD);
        } else {
            if (l0 >= 1) h0 = dot_row(xb + (size_t)(l0 - 1) * Dn, mem_s + m3 * MPAD);
        }
    }
    if (is_gemm) gemm_chunk(xs, mem_s, gsm, d4b, q, kc);
    __syncthreads();

    // ==================== single-barrier pipelined loop ====================
    // phase ci: argmax_ci | GEMM_{ci+1} | gather_{ci-1} | cp.async stage xs_{ci+2}
    for (int ci = 0; ci <= nc; ci++) {
        const int cur = ci & 1;
        const bool gemm_act = (ci + 1 < nc);

        // stage xs_{ci+2} into xs[cur] (async; GEMM this phase reads xs[cur^1])
        if (ci + 2 < nc) {
            int r = tid >> 6, c = tid & 63;
            cpasync16(smem_u32(xs + cur * XBUF + r * Dn + c * 4),
                      xb + (size_t)(l0 + (ci + 2) * CH + r) * Dn + c * 4);
        }

        // argmax_ci (all 512 threads, item = tid) -> best[cur]
        if (ci < nc) {
            const float* gc = gsm + cur * GBUF;
            float sc[3];
            #pragma unroll
            for (int n = 0; n < 3; n++) {
                int row = pa + n - 2;
                float g;
                if (row < 0) g = (n == 0) ? h0 : h1;   // only pa<=1 hits this
                else         g = gc[row * ROWS + m3 + n];
                sc[n] = g + bias_s[m3 + n];
            }
            int   bn = 0;
            float bv = sc[0];
            if (sc[1] > bv) { bv = sc[1]; bn = 1; }
            if (sc[2] > bv) { bv = sc[2]; bn = 2; }
            best_s[cur * NT + tid] = (unsigned short)((m3 + bn) * MPAD);
            // carry history for next chunk (rows 6,7 of current G)
            if (pa == 0) { h0 = gc[6 * ROWS + m3]; h1 = gc[7 * ROWS + m3 + 1]; }
            else if (pa == 1) { h0 = gc[7 * ROWS + m3]; }
        }

        if (is_gemm && gemm_act) {
            gemm_chunk(xs + (cur ^ 1) * XBUF, mem_s,
                       gsm + (cur ^ 1) * GBUF, d4b, q, kc);
        } else if (ci >= 1) {
            // gather_{ci-1}: reads best[cur^1]
            const unsigned short* bprev = best_s + (cur ^ 1) * NT;
            float* og = out + (orow0 + l0 + (size_t)(ci - 1) * CH) * Dn;
            if (gemm_act) {
                // middle phases: 512 items over 416 consumer threads
                int t = tid - GT;
                gather_one(mem_s, bprev + (t >> 6) * SLOTS,
                           og + (size_t)(t >> 6) * Dn, t & 63);
                if (t < GT) {
                    int t2 = t + 416;
                    gather_one(mem_s, bprev + (t2 >> 6) * SLOTS,
                               og + (size_t)(t2 >> 6) * Dn, t2 & 63);
                }
            } else {
                // tail phases (no GEMM): all 512 threads, 1 item each
                gather_one(mem_s, bprev + (tid >> 6) * SLOTS,
                           og + (size_t)(tid >> 6) * Dn, tid & 63);
            }
        }

        asm volatile("cp.async.wait_all;" ::: "memory");
        __syncthreads();
    }
}

extern "C" void kernel_launch(void* const* d_in, const int* in_sizes, int n_in,
                              void* d_out, int out_size)
{
    const float* x    = (const float*)d_in[0];   // (4, 2048, 256) f32
    const float* mem  = (const float*)d_in[1];   // (64, 3, 256)   f32
    const float* bias = (const float*)d_in[2];   // (64, 3)        f32
    float* out        = (float*)d_out;           // (4, 2048, 256) f32

    (void)in_sizes; (void)n_in; (void)out_size;

    const int smem_bytes = SMEM_WORDS * (int)sizeof(float);   // 231168
    cudaFuncSetAttribute(pnm_kernel,
                         cudaFuncAttributeMaxDynamicSharedMemorySize,
                         smem_bytes);

    pnm_kernel<<<Bn * TILES_PER_B, NT, smem_bytes>>>(x, mem, bias, out);
}

// round 16
// speedup vs baseline: 1.1122x; 1.1122x over previous
#include <cuda_runtime.h>

// Problem constants
#define Bn 4
#define Ln 2048
#define Dn 256
#define SLOTS 64
#define ROWS 192          // SLOTS * 3
#define MPAD 260          // padded stride (words): conflict-free GEMM m-loads
#define TILE 56           // 4 * 37 = 148 blocks = one full wave
#define CH 8              // positions per chunk
#define NT 512            // 16 warps: 6 GEMM + 10 gather (all do argmax)
#define TILES_PER_B 37
#define GBUF (CH * ROWS)  // 1536 words per G buffer
#define XBUF (CH * Dn)    // 2048 words per x buffer

// smem layout (words)
#define OFF_GSM  (ROWS * MPAD)                 // 49920 : gsm[2][8][192]
#define OFF_BIAS (OFF_GSM + 2 * GBUF)          // +3072
#define OFF_BEST (OFF_BIAS + ROWS)             // +192  : best[2][512] ushort = 512 words
#define OFF_XS   (OFF_BEST + 512)              // xs[2][8][256]
#define SMEM_WORDS (OFF_XS + 2 * XBUF)         // 57792 words = 231168 B

typedef unsigned long long u64;
typedef unsigned int u32;

__device__ __forceinline__ void bar_gemm() {   // 6 GEMM warps only
    asm volatile("bar.sync 1, 192;" ::: "memory");
}
__device__ __forceinline__ u64 fma2(u64 a, u64 b, u64 c) {
    u64 d;
    asm("fma.rn.f32x2 %0, %1, %2, %3;" : "=l"(d) : "l"(a), "l"(b), "l"(c));
    return d;
}
__device__ __forceinline__ u64 add2(u64 a, u64 b) {
    u64 d;
    asm("add.rn.f32x2 %0, %1, %2;" : "=l"(d) : "l"(a), "l"(b));
    return d;
}
__device__ __forceinline__ float hsum2(u64 a) {
    float lo, hi;
    asm("mov.b64 {%0,%1}, %2;" : "=f"(lo), "=f"(hi) : "l"(a));
    return lo + hi;
}
__device__ __forceinline__ u32 smem_u32(const void* p) {
    u32 a;
    asm("{ .reg .u64 t; cvta.to.shared.u64 t, %1; cvt.u32.u64 %0, t; }"
        : "=r"(a) : "l"(p));
    return a;
}
__device__ __forceinline__ void cpasync16(u32 dst, const void* src) {
    asm volatile("cp.async.cg.shared.global [%0], [%1], 16;" :: "r"(dst), "l"(src));
}

// full-K dot of gmem x-row with smem mem-row (for head seeds)
__device__ __forceinline__ float dot_row(const float* xrow, const float* mrow) {
    const ulonglong2* mp = (const ulonglong2*)mrow;
    const ulonglong2* xp = (const ulonglong2*)xrow;
    u64 a0 = 0ULL, a1 = 0ULL;
    #pragma unroll 8
    for (int d4 = 0; d4 < 64; ++d4) {
        ulonglong2 m = mp[d4], xv = xp[d4];
        a0 = fma2(m.x, xv.x, a0);
        a1 = fma2(m.y, xv.y, a1);
    }
    return hsum2(add2(a0, a1));
}

// GEMM slice: 2 cols (j0, j0+96), K-half, 8 rows, x via broadcast LDS.
// kc1 writes gsm, bar, kc0 adds (combine folded in; no part buffer).
__device__ __forceinline__ void gemm_chunk(
    const float* __restrict__ xs,
    const ulonglong2* __restrict__ mp0,
    const ulonglong2* __restrict__ mp1,
    float* __restrict__ gdst, int d4b, int j0, int kc)
{
    const ulonglong2* xp = (const ulonglong2*)xs;
    u64 a0[8], a1[8];
    #pragma unroll
    for (int r = 0; r < 8; r++) { a0[r] = 0ULL; a1[r] = 0ULL; }
    #pragma unroll 4
    for (int d4 = d4b; d4 < d4b + 32; ++d4) {
        ulonglong2 m0 = mp0[d4];               // 4-phase LDS.128 (MPAD-padded)
        ulonglong2 m1 = mp1[d4];
        #pragma unroll
        for (int r = 0; r < 8; r++) {
            ulonglong2 xv = xp[r * 64 + d4];   // warp-uniform broadcast LDS.128
            a0[r] = fma2(m0.x, xv.x, a0[r]);
            a0[r] = fma2(m0.y, xv.y, a0[r]);
            a1[r] = fma2(m1.x, xv.x, a1[r]);
            a1[r] = fma2(m1.y, xv.y, a1[r]);
        }
    }
    if (kc == 1) {
        #pragma unroll
        for (int r = 0; r < 8; r++) {
            gdst[r * ROWS + j0]      = hsum2(a0[r]);
            gdst[r * ROWS + j0 + 96] = hsum2(a1[r]);
        }
    }
    bar_gemm();
    if (kc == 0) {
        #pragma unroll
        for (int r = 0; r < 8; r++) {
            gdst[r * ROWS + j0]      += hsum2(a0[r]);
            gdst[r * ROWS + j0 + 96] += hsum2(a1[r]);
        }
    }
}

// gather one (p, d4): sum 64 selected rows (ushort premult indices, broadcast)
__device__ __forceinline__ void gather_one(
    const float* __restrict__ mem_s, const unsigned short* __restrict__ bp,
    float* __restrict__ outp, int d4)
{
    const uint4* ip = (const uint4*)bp;        // 8 x uint4 = 64 ushorts
    u64 ax[4] = {0ULL, 0ULL, 0ULL, 0ULL};
    u64 ay[4] = {0ULL, 0ULL, 0ULL, 0ULL};
    #pragma unroll
    for (int g = 0; g < 8; g++) {
        uint4 w = ip[g];                       // warp-uniform broadcast
        int q = g & 3;
        ulonglong2 v;
        #define PNM_ROW(IDX) \
            v = ((const ulonglong2*)(mem_s + (IDX)))[d4]; \
            ax[q] = add2(ax[q], v.x); ay[q] = add2(ay[q], v.y);
        PNM_ROW(w.x & 0xFFFFu)  PNM_ROW(w.x >> 16)
        PNM_ROW(w.y & 0xFFFFu)  PNM_ROW(w.y >> 16)
        PNM_ROW(w.z & 0xFFFFu)  PNM_ROW(w.z >> 16)
        PNM_ROW(w.w & 0xFFFFu)  PNM_ROW(w.w >> 16)
        #undef PNM_ROW
    }
    u64 s0 = add2(add2(ax[0], ax[1]), add2(ax[2], ax[3]));
    u64 s1 = add2(add2(ay[0], ay[1]), add2(ay[2], ay[3]));
    float x0, x1, y0, y1;
    asm("mov.b64 {%0,%1}, %2;" : "=f"(x0), "=f"(x1) : "l"(s0));
    asm("mov.b64 {%0,%1}, %2;" : "=f"(y0), "=f"(y1) : "l"(s1));
    ((float4*)outp)[d4] = make_float4(x0, x1, y0, y1);
}

__global__ void __launch_bounds__(NT, 1)
pnm_kernel(const float* __restrict__ x,
           const float* __restrict__ mem,
           const float* __restrict__ bias,
           float* __restrict__ out)
{
    extern __shared__ float smem[];
    float* mem_s  = smem;                               // [ROWS][MPAD]
    float* gsm    = smem + OFF_GSM;                     // [2][8][192]
    float* bias_s = smem + OFF_BIAS;                    // [192]
    unsigned short* best_s = (unsigned short*)(smem + OFF_BEST); // [2][512]
    float* xs     = smem + OFF_XS;                      // [2][8][256]

    const int tid  = threadIdx.x;
    const int b    = blockIdx.x / TILES_PER_B;
    const int l0   = (blockIdx.x % TILES_PER_B) * TILE;
    const int lend = (l0 + TILE < Ln) ? (l0 + TILE) : Ln;
    const int nc   = (lend - l0) / CH;                  // 7 or 4 (always exact)

    const float* xb = x + (size_t)b * Ln * Dn;
    const size_t orow0 = (size_t)b * Ln;

    // ---- prologue 1: stage mem_s + bias + xs[0] + xs[1] ----
    for (int i = tid; i < ROWS * (Dn / 4); i += NT) {
        int r = i >> 6, c = i & 63;
        ((float4*)(mem_s + r * MPAD))[c] = ((const float4*)mem)[i];
    }
    if (tid < ROWS) bias_s[tid] = bias[tid];
    {
        int r = tid >> 6, c = tid & 63;
        ((float4*)(xs + r * Dn))[c] =
            ((const float4*)(xb + (size_t)(l0 + r) * Dn))[c];
        ((float4*)(xs + XBUF + r * Dn))[c] =
            ((const float4*)(xb + (size_t)(l0 + CH + r) * Dn))[c];
    }
    __syncthreads();

    // GEMM decomposition: 192 threads = 96 col-pairs x 2 K-halves (kc warp-uniform)
    const bool is_gemm = (tid < 192);
    const int  q  = tid % 96;
    const int  kc = (tid / 96) & 1;
    const ulonglong2* mp0 = (const ulonglong2*)(mem_s + q * MPAD);
    const ulonglong2* mp1 = (const ulonglong2*)(mem_s + (q + 96) * MPAD);
    const int d4b = kc * 32;

    // argmax identity (fixed across phases; h-regs live for tid<128)
    const int pa = tid >> 6;                   // position within chunk
    const int m3 = (tid & 63) * 3;
    float h0 = 0.f, h1 = 0.f;                  // boundary G (p==0: n0,n1; p==1: n0)

    // ---- prologue 2: h seeds (tid<128) + GEMM chunk 0 -> gsm[0] ----
    if (tid < 128) {
        if (pa == 0) {
            if (l0 >= 2) h0 = dot_row(xb + (size_t)(l0 - 2) * Dn, mem_s + m3 * MPAD);
            if (l0 >= 1) h1 = dot_row(xb + (size_t)(l0 - 1) * Dn, mem_s + (m3 + 1) * MPAD);
        } else {
            if (l0 >= 1) h0 = dot_row(xb + (size_t)(l0 - 1) * Dn, mem_s + m3 * MPAD);
        }
    }
    if (is_gemm) gemm_chunk(xs, mp0, mp1, gsm, d4b, q, kc);
    __syncthreads();

    // ==================== single-barrier pipelined loop ====================
    // phase ci: argmax_ci | GEMM_{ci+1} | gather_{ci-1} | cp.async stage xs_{ci+2}
    for (int ci = 0; ci <= nc; ci++) {
        const int cur = ci & 1;
        const bool gemm_act = (ci + 1 < nc);

        // stage xs_{ci+2} into xs[cur] (async; GEMM this phase reads xs[cur^1])
        if (ci + 2 < nc) {
            int r = tid >> 6, c = tid & 63;
            cpasync16(smem_u32(xs + cur * XBUF + r * Dn + c * 4),
                      xb + (size_t)(l0 + (ci + 2) * CH + r) * Dn + c * 4);
        }

        // argmax_ci (all 512 threads, item = tid) -> best[cur]
        if (ci < nc) {
            const float* gc = gsm + cur * GBUF;
            float sc[3];
            #pragma unroll
            for (int n = 0; n < 3; n++) {
                int row = pa + n - 2;
                float g;
                if (row < 0) g = (n == 0) ? h0 : h1;   // only pa<=1 hits this
                else         g = gc[row * ROWS + m3 + n];
                sc[n] = g + bias_s[m3 + n];
            }
            int   bn = 0;
            float bv = sc[0];
            if (sc[1] > bv) { bv = sc[1]; bn = 1; }
            if (sc[2] > bv) { bv = sc[2]; bn = 2; }
            best_s[cur * NT + tid] = (unsigned short)((m3 + bn) * MPAD);
            // carry history for next chunk (rows 6,7 of current G)
            if (pa == 0) { h0 = gc[6 * ROWS + m3]; h1 = gc[7 * ROWS + m3 + 1]; }
            else if (pa == 1) { h0 = gc[7 * ROWS + m3]; }
        }

        // gather_{ci-1}: reads best[cur^1], every thread exactly ONE item
        const unsigned short* bprev = best_s + (cur ^ 1) * NT;
        float* og = out + (orow0 + l0 + (size_t)(ci - 1) * CH) * Dn;

        if (is_gemm) {
            if (gemm_act)
                gemm_chunk(xs + (cur ^ 1) * XBUF, mp0, mp1,
                           gsm + (cur ^ 1) * GBUF, d4b, q, kc);
            if (ci >= 1) {
                // GEMM threads take items 320..511 (middle) or tid (tail)
                int item = gemm_act ? (320 + tid) : tid;
                gather_one(mem_s, bprev + (item >> 6) * SLOTS,
                           og + (size_t)(item >> 6) * Dn, item & 63);
            }
        } else if (ci >= 1) {
            int item = gemm_act ? (tid - 192) : tid;   // 0..319 (middle) or tid (tail)
            gather_one(mem_s, bprev + (item >> 6) * SLOTS,
                       og + (size_t)(item >> 6) * Dn, item & 63);
        }

        asm volatile("cp.async.wait_all;" ::: "memory");
        __syncthreads();
    }
}

extern "C" void kernel_launch(void* const* d_in, const int* in_sizes, int n_in,
                              void* d_out, int out_size)
{
    const float* x    = (const float*)d_in[0];   // (4, 2048, 256) f32
    const float* mem  = (const float*)d_in[1];   // (64, 3, 256)   f32
    const float* bias = (const float*)d_in[2];   // (64, 3)        f32
    float* out        = (float*)d_out;           // (4, 2048, 256) f32

    (void)in_sizes; (void)n_in; (void)out_size;

    const int smem_bytes = SMEM_WORDS * (int)sizeof(float);   // 231168
    cudaFuncSetAttribute(pnm_kernel,
                         cudaFuncAttributeMaxDynamicSharedMemorySize,
                         smem_bytes);

    pnm_kernel<<<Bn * TILES_PER_B, NT, smem_bytes>>>(x, mem, bias, out);
}

// round 17
// speedup vs baseline: 1.1295x; 1.0155x over previous
#include <cuda_runtime.h>

// Problem constants
#define Bn 4
#define Ln 2048
#define Dn 256
#define SLOTS 64
#define ROWS 192          // SLOTS * 3
#define MPAD 260          // padded stride (words): conflict-free GEMM m-loads
#define TILE 56           // 4 * 37 = 148 blocks = one full wave
#define CH 8              // positions per chunk
#define NT 512            // 16 warps: 6 GEMM + 10 gather (all do argmax)
#define TILES_PER_B 37
#define GBUF (CH * ROWS)  // 1536 words per G buffer
#define XBUF (CH * Dn)    // 2048 words per x buffer

// smem layout (words)
#define OFF_GSM  (ROWS * MPAD)                 // 49920 : gsm[2][8][192]
#define OFF_BIAS (OFF_GSM + 2 * GBUF)          // +3072
#define OFF_BEST (OFF_BIAS + ROWS)             // +192  : best[2][512] ushort = 512 words
#define OFF_XS   (OFF_BEST + 512)              // xs[2][8][256]
#define SMEM_WORDS (OFF_XS + 2 * XBUF)         // 57792 words = 231168 B

typedef unsigned long long u64;
typedef unsigned int u32;

__device__ __forceinline__ void bar_gemm() {   // 6 GEMM warps only
    asm volatile("bar.sync 1, 192;" ::: "memory");
}
__device__ __forceinline__ u64 fma2(u64 a, u64 b, u64 c) {
    u64 d;
    asm("fma.rn.f32x2 %0, %1, %2, %3;" : "=l"(d) : "l"(a), "l"(b), "l"(c));
    return d;
}
__device__ __forceinline__ u64 add2(u64 a, u64 b) {
    u64 d;
    asm("add.rn.f32x2 %0, %1, %2;" : "=l"(d) : "l"(a), "l"(b));
    return d;
}
__device__ __forceinline__ float hsum2(u64 a) {
    float lo, hi;
    asm("mov.b64 {%0,%1}, %2;" : "=f"(lo), "=f"(hi) : "l"(a));
    return lo + hi;
}
__device__ __forceinline__ u32 smem_u32(const void* p) {
    u32 a;
    asm("{ .reg .u64 t; cvta.to.shared.u64 t, %1; cvt.u32.u64 %0, t; }"
        : "=r"(a) : "l"(p));
    return a;
}
__device__ __forceinline__ void cpasync16(u32 dst, const void* src) {
    asm volatile("cp.async.cg.shared.global [%0], [%1], 16;" :: "r"(dst), "l"(src));
}

// full-K dot of gmem x-row with smem mem-row (for head seeds)
__device__ __forceinline__ float dot_row(const float* xrow, const float* mrow) {
    const ulonglong2* mp = (const ulonglong2*)mrow;
    const ulonglong2* xp = (const ulonglong2*)xrow;
    u64 a0 = 0ULL, a1 = 0ULL;
    #pragma unroll 8
    for (int d4 = 0; d4 < 64; ++d4) {
        ulonglong2 m = mp[d4], xv = xp[d4];
        a0 = fma2(m.x, xv.x, a0);
        a1 = fma2(m.y, xv.y, a1);
    }
    return hsum2(add2(a0, a1));
}

// GEMM slice: 2 cols (j0, j0+96), K-half, 8 rows, x via broadcast LDS.
// kc1 writes gsm, bar, kc0 adds (combine folded in; no part buffer).
__device__ __forceinline__ void gemm_chunk(
    const float* __restrict__ xs,
    const ulonglong2* __restrict__ mp0,
    const ulonglong2* __restrict__ mp1,
    float* __restrict__ gdst, int d4b, int j0, int kc)
{
    const ulonglong2* xp = (const ulonglong2*)xs;
    u64 a0[8], a1[8];
    #pragma unroll
    for (int r = 0; r < 8; r++) { a0[r] = 0ULL; a1[r] = 0ULL; }
    #pragma unroll 4
    for (int d4 = d4b; d4 < d4b + 32; ++d4) {
        ulonglong2 m0 = mp0[d4];               // 4-phase LDS.128 (MPAD-padded)
        ulonglong2 m1 = mp1[d4];
        #pragma unroll
        for (int r = 0; r < 8; r++) {
            ulonglong2 xv = xp[r * 64 + d4];   // warp-uniform broadcast LDS.128
            a0[r] = fma2(m0.x, xv.x, a0[r]);
            a0[r] = fma2(m0.y, xv.y, a0[r]);
            a1[r] = fma2(m1.x, xv.x, a1[r]);
            a1[r] = fma2(m1.y, xv.y, a1[r]);
        }
    }
    if (kc == 1) {
        #pragma unroll
        for (int r = 0; r < 8; r++) {
            gdst[r * ROWS + j0]      = hsum2(a0[r]);
            gdst[r * ROWS + j0 + 96] = hsum2(a1[r]);
        }
    }
    bar_gemm();
    if (kc == 0) {
        #pragma unroll
        for (int r = 0; r < 8; r++) {
            gdst[r * ROWS + j0]      += hsum2(a0[r]);
            gdst[r * ROWS + j0 + 96] += hsum2(a1[r]);
        }
    }
}

// gather one (p, d4): sum 64 selected rows (ushort premult indices, broadcast)
__device__ __forceinline__ void gather_one(
    const float* __restrict__ mem_s, const unsigned short* __restrict__ bp,
    float* __restrict__ outp, int d4)
{
    const uint4* ip = (const uint4*)bp;        // 8 x uint4 = 64 ushorts
    u64 ax[4] = {0ULL, 0ULL, 0ULL, 0ULL};
    u64 ay[4] = {0ULL, 0ULL, 0ULL, 0ULL};
    #pragma unroll
    for (int g = 0; g < 8; g++) {
        uint4 w = ip[g];                       // warp-uniform broadcast
        int q = g & 3;
        ulonglong2 v;
        #define PNM_ROW(IDX) \
            v = ((const ulonglong2*)(mem_s + (IDX)))[d4]; \
            ax[q] = add2(ax[q], v.x); ay[q] = add2(ay[q], v.y);
        PNM_ROW(w.x & 0xFFFFu)  PNM_ROW(w.x >> 16)
        PNM_ROW(w.y & 0xFFFFu)  PNM_ROW(w.y >> 16)
        PNM_ROW(w.z & 0xFFFFu)  PNM_ROW(w.z >> 16)
        PNM_ROW(w.w & 0xFFFFu)  PNM_ROW(w.w >> 16)
        #undef PNM_ROW
    }
    u64 s0 = add2(add2(ax[0], ax[1]), add2(ax[2], ax[3]));
    u64 s1 = add2(add2(ay[0], ay[1]), add2(ay[2], ay[3]));
    float x0, x1, y0, y1;
    asm("mov.b64 {%0,%1}, %2;" : "=f"(x0), "=f"(x1) : "l"(s0));
    asm("mov.b64 {%0,%1}, %2;" : "=f"(y0), "=f"(y1) : "l"(s1));
    ((float4*)outp)[d4] = make_float4(x0, x1, y0, y1);
}

__global__ void __launch_bounds__(NT, 1)
pnm_kernel(const float* __restrict__ x,
           const float* __restrict__ mem,
           const float* __restrict__ bias,
           float* __restrict__ out)
{
    extern __shared__ float smem[];
    float* mem_s  = smem;                               // [ROWS][MPAD]
    float* gsm    = smem + OFF_GSM;                     // [2][8][192]
    float* bias_s = smem + OFF_BIAS;                    // [192]
    unsigned short* best_s = (unsigned short*)(smem + OFF_BEST); // [2][512]
    float* xs     = smem + OFF_XS;                      // [2][8][256]

    const int tid  = threadIdx.x;
    const int b    = blockIdx.x / TILES_PER_B;
    const int l0   = (blockIdx.x % TILES_PER_B) * TILE;
    const int lend = (l0 + TILE < Ln) ? (l0 + TILE) : Ln;
    const int nc   = (lend - l0) / CH;                  // 7 or 4 (always exact)

    const float* xb = x + (size_t)b * Ln * Dn;
    const size_t orow0 = (size_t)b * Ln;

    // ---- prologue 1: stage mem_s + bias + xs[0] + xs[1] ----
    for (int i = tid; i < ROWS * (Dn / 4); i += NT) {
        int r = i >> 6, c = i & 63;
        ((float4*)(mem_s + r * MPAD))[c] = ((const float4*)mem)[i];
    }
    if (tid < ROWS) bias_s[tid] = bias[tid];
    {
        int r = tid >> 6, c = tid & 63;
        ((float4*)(xs + r * Dn))[c] =
            ((const float4*)(xb + (size_t)(l0 + r) * Dn))[c];
        ((float4*)(xs + XBUF + r * Dn))[c] =
            ((const float4*)(xb + (size_t)(l0 + CH + r) * Dn))[c];
    }
    __syncthreads();

    // GEMM decomposition: 192 threads = 96 col-pairs x 2 K-halves (kc warp-uniform)
    const bool is_gemm = (tid < 192);
    const int  q  = tid % 96;
    const int  kc = (tid / 96) & 1;
    const ulonglong2* mp0 = (const ulonglong2*)(mem_s + q * MPAD);
    const ulonglong2* mp1 = (const ulonglong2*)(mem_s + (q + 96) * MPAD);
    const int d4b = kc * 32;

    // argmax identity (fixed across phases; h-regs live for tid<128)
    const int pa = tid >> 6;                   // position within chunk
    const int m3 = (tid & 63) * 3;
    float h0 = 0.f, h1 = 0.f;                  // boundary G (p==0: n0,n1; p==1: n0)

    // ---- prologue 2: h seeds (tid<128) + GEMM chunk 0 -> gsm[0] ----
    if (tid < 128) {
        if (pa == 0) {
            if (l0 >= 2) h0 = dot_row(xb + (size_t)(l0 - 2) * Dn, mem_s + m3 * MPAD);
            if (l0 >= 1) h1 = dot_row(xb + (size_t)(l0 - 1) * Dn, mem_s + (m3 + 1) * MPAD);
        } else {
            if (l0 >= 1) h0 = dot_row(xb + (size_t)(l0 - 1) * Dn, mem_s + m3 * MPAD);
        }
    }
    if (is_gemm) gemm_chunk(xs, mp0, mp1, gsm, d4b, q, kc);
    __syncthreads();

    // ==================== single-barrier pipelined loop ====================
    // phase ci: argmax_ci | GEMM_{ci+1} | gather_{ci-1} | cp.async stage xs_{ci+2}
    for (int ci = 0; ci <= nc; ci++) {
        const int cur = ci & 1;
        const bool gemm_act = (ci + 1 < nc);

        // stage xs_{ci+2} into xs[cur] (async; GEMM this phase reads xs[cur^1])
        if (ci + 2 < nc) {
            int r = tid >> 6, c = tid & 63;
            cpasync16(smem_u32(xs + cur * XBUF + r * Dn + c * 4),
                      xb + (size_t)(l0 + (ci + 2) * CH + r) * Dn + c * 4);
        }

        // argmax_ci (all 512 threads, item = tid) -> best[cur]
        if (ci < nc) {
            const float* gc = gsm + cur * GBUF;
            float sc[3];
            #pragma unroll
            for (int n = 0; n < 3; n++) {
                int row = pa + n - 2;
                float g;
                if (row < 0) g = (n == 0) ? h0 : h1;   // only pa<=1 hits this
                else         g = gc[row * ROWS + m3 + n];
                sc[n] = g + bias_s[m3 + n];
            }
            int   bn = 0;
            float bv = sc[0];
            if (sc[1] > bv) { bv = sc[1]; bn = 1; }
            if (sc[2] > bv) { bv = sc[2]; bn = 2; }
            best_s[cur * NT + tid] = (unsigned short)((m3 + bn) * MPAD);
            // carry history for next chunk (rows 6,7 of current G)
            if (pa == 0) { h0 = gc[6 * ROWS + m3]; h1 = gc[7 * ROWS + m3 + 1]; }
            else if (pa == 1) { h0 = gc[7 * ROWS + m3]; }
        }

        if (is_gemm && gemm_act) {
            gemm_chunk(xs + (cur ^ 1) * XBUF, mp0, mp1,
                       gsm + (cur ^ 1) * GBUF, d4b, q, kc);
        } else if (ci >= 1) {
            // gather_{ci-1}: reads best[cur^1]
            const unsigned short* bprev = best_s + (cur ^ 1) * NT;
            float* og = out + (orow0 + l0 + (size_t)(ci - 1) * CH) * Dn;
            if (gemm_act) {
                // middle phases (R14 layout): 512 items over 320 consumer threads
                int t = tid - 192;
                gather_one(mem_s, bprev + (t >> 6) * SLOTS,
                           og + (size_t)(t >> 6) * Dn, t & 63);
                if (t < 192) {
                    int t2 = t + 320;
                    gather_one(mem_s, bprev + (t2 >> 6) * SLOTS,
                               og + (size_t)(t2 >> 6) * Dn, t2 & 63);
                }
            } else {
                // tail phases (no GEMM): all 512 threads, exactly 1 item each
                gather_one(mem_s, bprev + (tid >> 6) * SLOTS,
                           og + (size_t)(tid >> 6) * Dn, tid & 63);
            }
        }

        asm volatile("cp.async.wait_all;" ::: "memory");
        __syncthreads();
    }
}

extern "C" void kernel_launch(void* const* d_in, const int* in_sizes, int n_in,
                              void* d_out, int out_size)
{
    const float* x    = (const float*)d_in[0];   // (4, 2048, 256) f32
    const float* mem  = (const float*)d_in[1];   // (64, 3, 256)   f32
    const float* bias = (const float*)d_in[2];   // (64, 3)        f32
    float* out        = (float*)d_out;           // (4, 2048, 256) f32

    (void)in_sizes; (void)n_in; (void)out_size;

    const int smem_bytes = SMEM_WORDS * (int)sizeof(float);   // 231168
    cudaFuncSetAttribute(pnm_kernel,
                         cudaFuncAttributeMaxDynamicSharedMemorySize,
                         smem_bytes);

    pnm_kernel<<<Bn * TILES_PER_B, NT, smem_bytes>>>(x, mem, bias, out);
}